// round 6
// baseline (speedup 1.0000x reference)
#include <cuda_runtime.h>

#define W_IMG 256
#define H_IMG 256
#define TILE 16
#define NG 8192
#define NSEG 4
#define SEG (NG / NSEG)
#define NTILE 256
#define CAP 512
#define MIN_W 1e-6f
#define LOG2E 1.4426950408889634f
#define NPIX (W_IMG * H_IMG)

__device__ float4 g_scratch[NSEG][NPIX];      // (cr,cg,cb,T) per segment per pixel
__device__ float4 g_l1[NSEG * NTILE * CAP];   // -mx, -my, a2, b2
__device__ float4 g_l2[NSEG * NTILE * CAP];   // c2, d, col.r, col.g
__device__ float  g_lb[NSEG * NTILE * CAP];   // col.b
__device__ int    g_cnt[NSEG * NTILE];        // padded entry count

__device__ __forceinline__ float ex2_fast(float x) {
    float y; asm("ex2.approx.f32 %0, %1;" : "=f"(y) : "f"(x)); return y;
}
__device__ __forceinline__ float lg2_fast(float x) {
    float y; asm("lg2.approx.f32 %0, %1;" : "=f"(y) : "f"(x)); return y;
}

// ---------- binning: one warp per (tile, depth-segment), depth order kept ----------
__global__ __launch_bounds__(256)
void gs_bin_kernel(const float* __restrict__ pxy,
                   const float* __restrict__ icov,
                   const float* __restrict__ radius,
                   const float* __restrict__ colors,
                   const float* __restrict__ opacity)
{
    const int wg   = blockIdx.x * 8 + (threadIdx.x >> 5);   // 0..1023 = seg*256 + tile
    const int lane = threadIdx.x & 31;
    const int tile = wg & (NTILE - 1);
    const int seg  = wg >> 8;
    const int tx   = tile & 15, ty = tile >> 4;
    const float tx0 = (float)(tx * TILE), tx1 = tx0 + (float)TILE;
    const float ty0 = (float)(ty * TILE), ty1 = ty0 + (float)TILE;
    const int lbase = wg * CAP;

    int cnt = 0;
    const int beg = seg * SEG, end = beg + SEG;
    for (int base = beg; base < end; base += 32) {           // SEG % 32 == 0
        const int g = base + lane;
        const float2 mp = ((const float2*)pxy)[g];
        const float  r  = radius[g];
        const bool keep = (floorf(mp.x - r) <= tx1) && (ceilf(mp.x + r) >= tx0)
                       && (floorf(mp.y - r) <= ty1) && (ceilf(mp.y + r) >= ty0);
        const unsigned m = __ballot_sync(0xffffffffu, keep);
        if (keep) {
            const int idx = cnt + __popc(m & ((1u << lane) - 1u));  // order-preserving
            if (idx < CAP) {
                const float4 ic = ((const float4*)icov)[g];
                const float a2 = -0.5f * LOG2E * ic.x;
                const float b2 = -LOG2E * ic.y;
                const float c2 = -0.5f * LOG2E * ic.w;
                const float d  = -lg2_fast(1.0f + ex2_fast(-LOG2E * opacity[g]));
                g_l1[lbase + idx] = make_float4(-mp.x, -mp.y, a2, b2);
                g_l2[lbase + idx] = make_float4(c2, d, colors[3*g+0], colors[3*g+1]);
                g_lb[lbase + idx] = colors[3*g+2];
            }
        }
        cnt += __popc(m);
    }
    cnt = min(cnt, CAP);
    const int padded = min((cnt + 7) & ~7, CAP);
    if (lane < padded - cnt) {                               // alpha == 0 sentinels
        g_l1[lbase + cnt + lane] = make_float4(0.0f, 0.0f, 0.0f, 0.0f);
        g_l2[lbase + cnt + lane] = make_float4(0.0f, -1e30f, 0.0f, 0.0f);
        g_lb[lbase + cnt + lane] = 0.0f;
    }
    if (lane == 0) g_cnt[wg] = padded;
}

// ---------- raster: one block per (tile, segment); no cull, minimal barriers ----------
__global__ __launch_bounds__(256)
void gs_raster_kernel()
{
    __shared__ float4 s_g1[256];
    __shared__ float4 s_g2[256];
    __shared__ float  s_cb[256];

    const int tid  = threadIdx.x;
    const int tile = blockIdx.x;                 // 0..255
    const int seg  = blockIdx.y;                 // 0..3
    const int tx   = tile & 15, ty = tile >> 4;

    const float fx = (float)(tx * TILE + (tid >> 4));
    const float fy = (float)(ty * TILE + (tid & 15));

    const int lid   = seg * NTILE + tile;
    const int n     = g_cnt[lid];                // multiple of 8
    const int lbase = lid * CAP;

    float T = 1.0f, cr = 0.0f, cg = 0.0f, cb = 0.0f;

    for (int base = 0; base < n; base += 256) {
        const int m = min(256, n - base);        // multiple of 8
        if (tid < m) {                           // coalesced chunk stage
            s_g1[tid] = g_l1[lbase + base + tid];
            s_g2[tid] = g_l2[lbase + base + tid];
            s_cb[tid] = g_lb[lbase + base + tid];
        }
        __syncthreads();

        if (T >= MIN_W) {
            for (int j = 0; j < m; j += 8) {
                float al[8];
                #pragma unroll
                for (int k = 0; k < 8; ++k) {    // independent alpha evals
                    const float4 g1 = s_g1[j + k];
                    const float4 g2 = s_g2[j + k];
                    const float dx = fx + g1.x;
                    const float dy = fy + g1.y;
                    float u = fmaf(g1.z, dx, g1.w * dy);
                    float q = fmaf(g2.x * dy, dy, g2.y);
                    q = fmaf(u, dx, q);
                    al[k] = ex2_fast(q);         // exp(-q/2)*sigmoid(op)
                }
                #pragma unroll
                for (int k = 0; k < 8; ++k) {    // short serial T-chain
                    const float Tn = fmaf(-al[k], T, T);
                    const float w  = (Tn >= MIN_W) ? T * al[k] : 0.0f;
                    const float4 g2 = s_g2[j + k];
                    cr = fmaf(w, g2.z, cr);
                    cg = fmaf(w, g2.w, cg);
                    cb = fmaf(w, s_cb[j + k], cb);
                    T = Tn;
                }
                if (T < MIN_W) break;            // monotone
            }
        }
        if (base + 256 < n) __syncthreads();
    }

    const int px = tx * TILE + (tid >> 4);
    const int py = ty * TILE + (tid & 15);
    g_scratch[seg][px * H_IMG + py] = make_float4(cr, cg, cb, T);
}

// ---------- combine ----------
__global__ __launch_bounds__(256)
void gs_combine_kernel(float* __restrict__ out)
{
    __shared__ float s[768];
    const int tid = threadIdx.x;
    const int i = blockIdx.x * 256 + tid;
    const float4 s0 = g_scratch[0][i];
    const float4 s1 = g_scratch[1][i];
    const float4 s2 = g_scratch[2][i];
    const float4 s3 = g_scratch[3][i];
    // color = c0 + T0*(c1 + T1*(c2 + T2*c3))
    float cr = fmaf(s2.w, s3.x, s2.x);
    float cg = fmaf(s2.w, s3.y, s2.y);
    float cb = fmaf(s2.w, s3.z, s2.z);
    cr = fmaf(s1.w, cr, s1.x);
    cg = fmaf(s1.w, cg, s1.y);
    cb = fmaf(s1.w, cb, s1.z);
    cr = fmaf(s0.w, cr, s0.x);
    cg = fmaf(s0.w, cg, s0.y);
    cb = fmaf(s0.w, cb, s0.z);
    s[3*tid + 0] = cr;
    s[3*tid + 1] = cg;
    s[3*tid + 2] = cb;
    __syncthreads();
    float4* ob = (float4*)(out + blockIdx.x * 768);   // coalesced vector stores
    if (tid < 192) ob[tid] = ((const float4*)s)[tid];
}

extern "C" void kernel_launch(void* const* d_in, const int* in_sizes, int n_in,
                              void* d_out, int out_size) {
    const float* pxy     = (const float*)d_in[0];
    const float* icov    = (const float*)d_in[1];
    const float* radius  = (const float*)d_in[2];
    const float* colors  = (const float*)d_in[3];
    const float* opacity = (const float*)d_in[4];
    float* out = (float*)d_out;

    gs_bin_kernel<<<128, 256>>>(pxy, icov, radius, colors, opacity);   // 1024 warps
    dim3 rgrid(NTILE, NSEG);
    gs_raster_kernel<<<rgrid, 256>>>();
    gs_combine_kernel<<<NPIX / 256, 256>>>(out);
}

// round 7
// speedup vs baseline: 1.0900x; 1.0900x over previous
#include <cuda_runtime.h>

#define W_IMG 256
#define H_IMG 256
#define TILE 16
#define NG 8192
#define NSEG 4
#define NCHUNK 16                 // subchunks of the depth list
#define CHUNKSZ (NG / NCHUNK)     // 512 gaussians per subchunk
#define CPS (NCHUNK / NSEG)       // 4 subchunks per raster segment
#define NTILE 256
#define CAP 512                   // worst-case survivors per subchunk
#define MIN_W 1e-6f
#define LOG2E 1.4426950408889634f
#define NPIX (W_IMG * H_IMG)

__device__ float4 g_scratch[NSEG][NPIX];        // (cr,cg,cb,T) per segment per pixel
__device__ float4 g_l1[NTILE * NCHUNK * CAP];   // -mx, -my, a2, b2
__device__ float4 g_l2[NTILE * NCHUNK * CAP];   // c2, d, col.r, col.g
__device__ float  g_lb[NTILE * NCHUNK * CAP];   // col.b
__device__ int    g_cnt[NTILE * NCHUNK];        // padded (x8) entry count

__device__ __forceinline__ float ex2_fast(float x) {
    float y; asm("ex2.approx.f32 %0, %1;" : "=f"(y) : "f"(x)); return y;
}
__device__ __forceinline__ float lg2_fast(float x) {
    float y; asm("lg2.approx.f32 %0, %1;" : "=f"(y) : "f"(x)); return y;
}

// ---------- bin: one warp per (tile, subchunk); depth order preserved ----------
__global__ __launch_bounds__(256)
void gs_bin_kernel(const float* __restrict__ pxy,
                   const float* __restrict__ icov,
                   const float* __restrict__ radius,
                   const float* __restrict__ colors,
                   const float* __restrict__ opacity)
{
    const int wid  = blockIdx.x * 8 + (threadIdx.x >> 5);   // 0..4095 = tile*16 + chunk
    const int lane = threadIdx.x & 31;
    const int tile = wid >> 4;
    const int chunk = wid & (NCHUNK - 1);
    const int tx = tile & 15, ty = tile >> 4;
    const float tx0 = (float)(tx * TILE), tx1 = tx0 + (float)TILE;
    const float ty0 = (float)(ty * TILE), ty1 = ty0 + (float)TILE;
    const int lbase = wid * CAP;
    const int beg = chunk * CHUNKSZ;

    int cnt = 0;
    #pragma unroll 4
    for (int it = 0; it < CHUNKSZ / 32; ++it) {
        const int g = beg + it * 32 + lane;
        const float2 mp = ((const float2*)pxy)[g];
        const float  r  = radius[g];
        const bool keep = (floorf(mp.x - r) <= tx1) && (ceilf(mp.x + r) >= tx0)
                       && (floorf(mp.y - r) <= ty1) && (ceilf(mp.y + r) >= ty0);
        const unsigned m = __ballot_sync(0xffffffffu, keep);
        if (keep) {
            const int idx = cnt + __popc(m & ((1u << lane) - 1u));  // order-preserving
            const float4 ic = ((const float4*)icov)[g];
            const float a2 = -0.5f * LOG2E * ic.x;
            const float b2 = -LOG2E * ic.y;
            const float c2 = -0.5f * LOG2E * ic.w;
            const float d  = -lg2_fast(1.0f + ex2_fast(-LOG2E * opacity[g])); // log2(sigmoid)
            g_l1[lbase + idx] = make_float4(-mp.x, -mp.y, a2, b2);
            g_l2[lbase + idx] = make_float4(c2, d, colors[3*g+0], colors[3*g+1]);
            g_lb[lbase + idx] = colors[3*g+2];
        }
        cnt += __popc(m);
    }
    const int padded = (cnt + 7) & ~7;           // <= CAP always (cnt <= 512)
    if (lane < padded - cnt) {                   // alpha == 0 sentinels
        g_l1[lbase + cnt + lane] = make_float4(0.0f, 0.0f, 0.0f, 0.0f);
        g_l2[lbase + cnt + lane] = make_float4(0.0f, -1e30f, 0.0f, 0.0f);
        g_lb[lbase + cnt + lane] = 0.0f;
    }
    if (lane == 0) g_cnt[wid] = padded;
}

// ---------- raster: block per (tile, segment); no barriers, no smem ----------
__global__ __launch_bounds__(256)
void gs_raster_kernel()
{
    const int tid  = threadIdx.x;
    const int tile = blockIdx.x;                 // 0..255
    const int seg  = blockIdx.y;                 // 0..3
    const int tx   = tile & 15, ty = tile >> 4;

    const float fx = (float)(tx * TILE + (tid >> 4));
    const float fy = (float)(ty * TILE + (tid & 15));

    float T = 1.0f, cr = 0.0f, cg = 0.0f, cb = 0.0f;

    #pragma unroll 1
    for (int c = 0; c < CPS; ++c) {              // 4 depth-ordered sub-lists
        const int wid   = (tile << 4) + seg * CPS + c;
        const int n     = g_cnt[wid];            // multiple of 8
        const int lbase = wid * CAP;

        for (int j = 0; j < n; j += 8) {
            float al[8];
            #pragma unroll
            for (int k = 0; k < 8; ++k) {        // independent alpha evals (broadcast LDG)
                const float4 g1 = __ldg(&g_l1[lbase + j + k]);
                const float4 g2 = __ldg(&g_l2[lbase + j + k]);
                const float dx = fx + g1.x;
                const float dy = fy + g1.y;
                float u = fmaf(g1.z, dx, g1.w * dy);
                float q = fmaf(g2.x * dy, dy, g2.y);
                q = fmaf(u, dx, q);
                al[k] = ex2_fast(q);             // exp(-q/2)*sigmoid(op)
            }
            #pragma unroll
            for (int k = 0; k < 8; ++k) {        // short serial T-chain
                const float Tn = fmaf(-al[k], T, T);
                const float w  = (Tn >= MIN_W) ? T * al[k] : 0.0f;
                const float4 g2 = __ldg(&g_l2[lbase + j + k]);
                cr = fmaf(w, g2.z, cr);
                cg = fmaf(w, g2.w, cg);
                cb = fmaf(w, __ldg(&g_lb[lbase + j + k]), cb);
                T = Tn;
            }
            if (T < MIN_W) break;                // monotone
        }
        if (T < MIN_W) break;
    }

    const int px = tx * TILE + (tid >> 4);
    const int py = ty * TILE + (tid & 15);
    g_scratch[seg][px * H_IMG + py] = make_float4(cr, cg, cb, T);
}

// ---------- combine ----------
__global__ __launch_bounds__(256)
void gs_combine_kernel(float* __restrict__ out)
{
    __shared__ float s[768];
    const int tid = threadIdx.x;
    const int i = blockIdx.x * 256 + tid;
    const float4 s0 = g_scratch[0][i];
    const float4 s1 = g_scratch[1][i];
    const float4 s2 = g_scratch[2][i];
    const float4 s3 = g_scratch[3][i];
    // color = c0 + T0*(c1 + T1*(c2 + T2*c3))
    float cr = fmaf(s2.w, s3.x, s2.x);
    float cg = fmaf(s2.w, s3.y, s2.y);
    float cb = fmaf(s2.w, s3.z, s2.z);
    cr = fmaf(s1.w, cr, s1.x);
    cg = fmaf(s1.w, cg, s1.y);
    cb = fmaf(s1.w, cb, s1.z);
    cr = fmaf(s0.w, cr, s0.x);
    cg = fmaf(s0.w, cg, s0.y);
    cb = fmaf(s0.w, cb, s0.z);
    s[3*tid + 0] = cr;
    s[3*tid + 1] = cg;
    s[3*tid + 2] = cb;
    __syncthreads();
    float4* ob = (float4*)(out + blockIdx.x * 768);   // coalesced vector stores
    if (tid < 192) ob[tid] = ((const float4*)s)[tid];
}

extern "C" void kernel_launch(void* const* d_in, const int* in_sizes, int n_in,
                              void* d_out, int out_size) {
    const float* pxy     = (const float*)d_in[0];
    const float* icov    = (const float*)d_in[1];
    const float* radius  = (const float*)d_in[2];
    const float* colors  = (const float*)d_in[3];
    const float* opacity = (const float*)d_in[4];
    float* out = (float*)d_out;

    gs_bin_kernel<<<512, 256>>>(pxy, icov, radius, colors, opacity);  // 4096 warps
    dim3 rgrid(NTILE, NSEG);
    gs_raster_kernel<<<rgrid, 256>>>();
    gs_combine_kernel<<<NPIX / 256, 256>>>(out);
}

// round 8
// speedup vs baseline: 1.5778x; 1.4476x over previous
#include <cuda_runtime.h>

#define W_IMG 256
#define H_IMG 256
#define TILE 16
#define NG 8192
#define NSEG 4
#define NCHUNK 16                 // depth subchunks
#define CHUNKSZ (NG / NCHUNK)     // 512
#define CPS (NCHUNK / NSEG)       // 4 sub-lists per raster segment
#define NTILE 256
#define CAP 512
#define MIN_W 1e-6f
#define LOG2E 1.4426950408889634f
#define NPIX (W_IMG * H_IMG)

typedef unsigned int u32;
typedef unsigned short u16;

__device__ float4 g_scratch[NSEG][NPIX];      // (cr,cg,cb,T)
__device__ u32    g_bbox[NG];                 // packed tile range: tlx, tly, 15-thx, 15-thy
__device__ float4 g_pa[NG];                   // -mx, -my, a2, b2
__device__ float4 g_pb[NG];                   // c2, d, col.r, col.g
__device__ float  g_pc[NG];                   // col.b
__device__ u16    g_idx[NTILE * NCHUNK * CAP];// per-(tile,chunk) surviving gaussian ids (depth order)
__device__ int    g_cnt[NTILE * NCHUNK];      // exact counts

__device__ __forceinline__ float ex2_fast(float x) {
    float y; asm("ex2.approx.f32 %0, %1;" : "=f"(y) : "f"(x)); return y;
}
__device__ __forceinline__ float lg2_fast(float x) {
    float y; asm("lg2.approx.f32 %0, %1;" : "=f"(y) : "f"(x)); return y;
}
__device__ __forceinline__ int iclamp(int v, int lo, int hi) {
    return v < lo ? lo : (v > hi ? hi : v);
}

// ---------------- prep: packed bbox + composite-ready payload (validated R5) ----------
__global__ __launch_bounds__(256)
void gs_prep_kernel(const float* __restrict__ pxy,
                    const float* __restrict__ icov,
                    const float* __restrict__ radius,
                    const float* __restrict__ colors,
                    const float* __restrict__ opacity)
{
    const int g = blockIdx.x * 256 + threadIdx.x;
    const float2 mp = ((const float2*)pxy)[g];
    const float  r  = radius[g];

    const float mnx = floorf(mp.x - r), mxx = ceilf(mp.x + r);
    const float mny = floorf(mp.y - r), mxy = ceilf(mp.y + r);
    const int tlx = (int)floorf((mnx - 1.0f) * 0.0625f);   // ceil((mnx-16)/16)
    const int thx = (int)floorf(mxx * 0.0625f);
    const int tly = (int)floorf((mny - 1.0f) * 0.0625f);
    const int thy = (int)floorf(mxy * 0.0625f);
    const u32 b0 = (u32)iclamp(tlx, 0, 255);
    const u32 b1 = (u32)iclamp(tly, 0, 255);
    const u32 b2 = (u32)iclamp(15 - thx, 0, 255);
    const u32 b3 = (u32)iclamp(15 - thy, 0, 255);
    g_bbox[g] = b0 | (b1 << 8) | (b2 << 16) | (b3 << 24);

    const float4 ic = ((const float4*)icov)[g];
    const float a2 = -0.5f * LOG2E * ic.x;
    const float bb = -LOG2E * ic.y;
    const float c2 = -0.5f * LOG2E * ic.w;
    const float d  = -lg2_fast(1.0f + ex2_fast(-LOG2E * opacity[g])); // log2(sigmoid)
    g_pa[g] = make_float4(-mp.x, -mp.y, a2, bb);
    g_pb[g] = make_float4(c2, d, colors[3*g+0], colors[3*g+1]);
    g_pc[g] = colors[3*g+2];
}

// ---------------- bin: warp per (tile, chunk-of-512); writes u16 indices ----------
__global__ __launch_bounds__(256)
void gs_bin_kernel()
{
    const int wid  = blockIdx.x * 8 + (threadIdx.x >> 5);   // 0..4095 = tile*16 + chunk
    const int lane = threadIdx.x & 31;
    const int tile = wid >> 4;
    const int chunk = wid & (NCHUNK - 1);
    const int tx = tile & 15, ty = tile >> 4;
    const u32 tvec = (u32)tx | ((u32)ty << 8) | ((u32)(15 - tx) << 16) | ((u32)(15 - ty) << 24);
    const int lbase = wid * CAP;
    const int beg = chunk * CHUNKSZ;

    int cnt = 0;
    #pragma unroll 4
    for (int it = 0; it < CHUNKSZ / 32; ++it) {
        const int g = beg + it * 32 + lane;
        const bool keep = (__vcmpleu4(g_bbox[g], tvec) == 0xffffffffu);
        const unsigned m = __ballot_sync(0xffffffffu, keep);
        if (keep) {
            const int idx = cnt + __popc(m & ((1u << lane) - 1u));  // order-preserving
            g_idx[lbase + idx] = (u16)g;
        }
        cnt += __popc(m);
    }
    if (lane == 0) g_cnt[wid] = cnt;
}

// ---------------- raster: block per (tile, segment); smem-staged composite ----------
__global__ __launch_bounds__(256)
void gs_raster_kernel()
{
    __shared__ float4 s_g1[256];
    __shared__ float4 s_g2[256];
    __shared__ float  s_cb[256];

    const int tid  = threadIdx.x;
    const int tile = blockIdx.x;
    const int seg  = blockIdx.y;
    const int tx   = tile & 15, ty = tile >> 4;

    const float fx = (float)(tx * TILE + (tid >> 4));
    const float fy = (float)(ty * TILE + (tid & 15));

    const int wbase = (tile << 4) + seg * CPS;     // 4 consecutive sub-lists, depth order
    const int c0 = g_cnt[wbase + 0];
    const int c1 = g_cnt[wbase + 1];
    const int c2 = g_cnt[wbase + 2];
    const int c3 = g_cnt[wbase + 3];
    const int o1 = c0, o2 = c0 + c1, o3 = o2 + c2;
    const int total = o3 + c3;

    float T = 1.0f, cr = 0.0f, cg = 0.0f, cb = 0.0f;

    for (int base = 0; base < total; base += 256) {
        // barrier (protects smem reuse) + block-wide early exit
        if (__syncthreads_count(T >= MIN_W) == 0) break;

        const int s = base + tid;
        if (s < total) {
            int c, pos;
            if (s >= o2) { c = (s >= o3) ? 3 : 2; pos = s - ((s >= o3) ? o3 : o2); }
            else         { c = (s >= o1) ? 1 : 0; pos = s - ((s >= o1) ? o1 : 0);  }
            const int gi = (int)g_idx[(wbase + c) * CAP + pos];
            s_g1[tid] = g_pa[gi];
            s_g2[tid] = g_pb[gi];
            s_cb[tid] = g_pc[gi];
        }
        const int m  = min(256, total - base);
        const int pm = (m + 7) & ~7;
        if (tid >= m && tid < pm) {               // alpha == 0 sentinels
            s_g1[tid] = make_float4(0.0f, 0.0f, 0.0f, 0.0f);
            s_g2[tid] = make_float4(0.0f, -1e30f, 0.0f, 0.0f);
            s_cb[tid] = 0.0f;
        }
        __syncthreads();

        if (T >= MIN_W) {
            for (int j = 0; j < pm; j += 8) {
                float al[8];
                #pragma unroll
                for (int k = 0; k < 8; ++k) {     // independent alpha evals (broadcast LDS)
                    const float4 g1 = s_g1[j + k];
                    const float4 g2 = s_g2[j + k];
                    const float dx = fx + g1.x;
                    const float dy = fy + g1.y;
                    float u = fmaf(g1.z, dx, g1.w * dy);
                    float q = fmaf(g2.x * dy, dy, g2.y);
                    q = fmaf(u, dx, q);
                    al[k] = ex2_fast(q);          // exp(-q/2)*sigmoid(op)
                }
                #pragma unroll
                for (int k = 0; k < 8; ++k) {     // short serial T-chain
                    const float Tn = fmaf(-al[k], T, T);
                    const float w  = (Tn >= MIN_W) ? T * al[k] : 0.0f;
                    const float4 g2 = s_g2[j + k];
                    cr = fmaf(w, g2.z, cr);
                    cg = fmaf(w, g2.w, cg);
                    cb = fmaf(w, s_cb[j + k], cb);
                    T = Tn;
                }
                if (T < MIN_W) break;             // monotone
            }
        }
    }

    const int px = tx * TILE + (tid >> 4);
    const int py = ty * TILE + (tid & 15);
    g_scratch[seg][px * H_IMG + py] = make_float4(cr, cg, cb, T);
}

// ---------------- combine: 512 blocks x 128 threads ----------
__global__ __launch_bounds__(128)
void gs_combine_kernel(float* __restrict__ out)
{
    __shared__ float s[384];
    const int tid = threadIdx.x;
    const int i = blockIdx.x * 128 + tid;
    const float4 s0 = g_scratch[0][i];
    const float4 s1 = g_scratch[1][i];
    const float4 s2 = g_scratch[2][i];
    const float4 s3 = g_scratch[3][i];
    // color = c0 + T0*(c1 + T1*(c2 + T2*c3))
    float cr = fmaf(s2.w, s3.x, s2.x);
    float cg = fmaf(s2.w, s3.y, s2.y);
    float cb = fmaf(s2.w, s3.z, s2.z);
    cr = fmaf(s1.w, cr, s1.x);
    cg = fmaf(s1.w, cg, s1.y);
    cb = fmaf(s1.w, cb, s1.z);
    cr = fmaf(s0.w, cr, s0.x);
    cg = fmaf(s0.w, cg, s0.y);
    cb = fmaf(s0.w, cb, s0.z);
    s[3*tid + 0] = cr;
    s[3*tid + 1] = cg;
    s[3*tid + 2] = cb;
    __syncthreads();
    float4* ob = (float4*)(out + blockIdx.x * 384);   // coalesced vector stores
    if (tid < 96) ob[tid] = ((const float4*)s)[tid];
}

extern "C" void kernel_launch(void* const* d_in, const int* in_sizes, int n_in,
                              void* d_out, int out_size) {
    const float* pxy     = (const float*)d_in[0];
    const float* icov    = (const float*)d_in[1];
    const float* radius  = (const float*)d_in[2];
    const float* colors  = (const float*)d_in[3];
    const float* opacity = (const float*)d_in[4];
    float* out = (float*)d_out;

    gs_prep_kernel<<<NG / 256, 256>>>(pxy, icov, radius, colors, opacity);
    gs_bin_kernel<<<512, 256>>>();                    // 4096 warps
    dim3 rgrid(NTILE, NSEG);
    gs_raster_kernel<<<rgrid, 256>>>();
    gs_combine_kernel<<<NPIX / 128, 128>>>(out);
}

// round 9
// speedup vs baseline: 1.6877x; 1.0696x over previous
#include <cuda_runtime.h>

#define W_IMG 256
#define H_IMG 256
#define TILE 16
#define NG 8192
#define NSEG 4
#define NCHUNK 32                 // depth subchunks
#define CHUNKSZ (NG / NCHUNK)     // 256
#define CPS (NCHUNK / NSEG)       // 8 sub-lists per raster segment
#define NTILE 256
#define CAP 256                   // max survivors per subchunk (== CHUNKSZ)
#define MIN_W 1e-6f
#define LOG2E 1.4426950408889634f
#define NPIX (W_IMG * H_IMG)

typedef unsigned int u32;
typedef unsigned short u16;

__device__ float4 g_scratch[NSEG][NPIX];      // (cr,cg,cb,T)
__device__ u32    g_bbox[NG];                 // packed tile range: tlx, tly, 15-thx, 15-thy
__device__ float4 g_pa[NG];                   // -mx, -my, a2, b2
__device__ float4 g_pb[NG];                   // c2, d, col.r, col.g
__device__ float  g_pc[NG];                   // col.b
__device__ u16    g_idx[NTILE * NCHUNK * CAP];// per-(tile,chunk) survivor ids (depth order)
__device__ int    g_cnt[NTILE * NCHUNK];      // exact counts
__device__ int    g_done[NTILE];              // zero-init; reset by winner each run

__device__ __forceinline__ float ex2_fast(float x) {
    float y; asm("ex2.approx.f32 %0, %1;" : "=f"(y) : "f"(x)); return y;
}
__device__ __forceinline__ float lg2_fast(float x) {
    float y; asm("lg2.approx.f32 %0, %1;" : "=f"(y) : "f"(x)); return y;
}
__device__ __forceinline__ int iclamp(int v, int lo, int hi) {
    return v < lo ? lo : (v > hi ? hi : v);
}
__device__ __forceinline__ float4 ldcg4(const float4* p) {
    float4 v;
    asm volatile("ld.global.cg.v4.f32 {%0,%1,%2,%3}, [%4];"
                 : "=f"(v.x), "=f"(v.y), "=f"(v.z), "=f"(v.w) : "l"(p));
    return v;
}

// ---------------- prep: packed bbox + composite-ready payload ----------
__global__ __launch_bounds__(256)
void gs_prep_kernel(const float* __restrict__ pxy,
                    const float* __restrict__ icov,
                    const float* __restrict__ radius,
                    const float* __restrict__ colors,
                    const float* __restrict__ opacity)
{
    const int g = blockIdx.x * 256 + threadIdx.x;
    const float2 mp = ((const float2*)pxy)[g];
    const float  r  = radius[g];

    const float mnx = floorf(mp.x - r), mxx = ceilf(mp.x + r);
    const float mny = floorf(mp.y - r), mxy = ceilf(mp.y + r);
    const int tlx = (int)floorf((mnx - 1.0f) * 0.0625f);   // ceil((mnx-16)/16)
    const int thx = (int)floorf(mxx * 0.0625f);
    const int tly = (int)floorf((mny - 1.0f) * 0.0625f);
    const int thy = (int)floorf(mxy * 0.0625f);
    const u32 b0 = (u32)iclamp(tlx, 0, 255);
    const u32 b1 = (u32)iclamp(tly, 0, 255);
    const u32 b2 = (u32)iclamp(15 - thx, 0, 255);
    const u32 b3 = (u32)iclamp(15 - thy, 0, 255);
    g_bbox[g] = b0 | (b1 << 8) | (b2 << 16) | (b3 << 24);

    const float4 ic = ((const float4*)icov)[g];
    const float a2 = -0.5f * LOG2E * ic.x;
    const float bb = -LOG2E * ic.y;
    const float c2 = -0.5f * LOG2E * ic.w;
    const float d  = -lg2_fast(1.0f + ex2_fast(-LOG2E * opacity[g])); // log2(sigmoid)
    g_pa[g] = make_float4(-mp.x, -mp.y, a2, bb);
    g_pb[g] = make_float4(c2, d, colors[3*g+0], colors[3*g+1]);
    g_pc[g] = colors[3*g+2];
}

// ---------------- bin: warp per (tile, chunk-of-256); u16 indices ----------
__global__ __launch_bounds__(256)
void gs_bin_kernel()
{
    const int wid  = blockIdx.x * 8 + (threadIdx.x >> 5);   // 0..8191 = tile*32 + chunk
    const int lane = threadIdx.x & 31;
    const int tile = wid >> 5;
    const int chunk = wid & (NCHUNK - 1);
    const int tx = tile & 15, ty = tile >> 4;
    const u32 tvec = (u32)tx | ((u32)ty << 8) | ((u32)(15 - tx) << 16) | ((u32)(15 - ty) << 24);
    const int lbase = wid * CAP;
    const int beg = chunk * CHUNKSZ;

    int cnt = 0;
    #pragma unroll
    for (int it = 0; it < CHUNKSZ / 32; ++it) {             // 8 iterations
        const int g = beg + it * 32 + lane;
        const bool keep = (__vcmpleu4(g_bbox[g], tvec) == 0xffffffffu);
        const unsigned m = __ballot_sync(0xffffffffu, keep);
        if (keep) {
            const int idx = cnt + __popc(m & ((1u << lane) - 1u));  // order-preserving
            g_idx[lbase + idx] = (u16)g;
        }
        cnt += __popc(m);
    }
    if (lane == 0) g_cnt[wid] = cnt;
}

// ---------------- raster + fused combine ----------
__global__ __launch_bounds__(256)
void gs_raster_kernel(float* __restrict__ out)
{
    __shared__ float4 s_g1[256];
    __shared__ float4 s_g2[256];
    __shared__ float  s_cb[256];
    __shared__ int    s_cnt[CPS];
    __shared__ int    s_ret;

    const int tid  = threadIdx.x;
    const int tile = blockIdx.x;
    const int seg  = blockIdx.y;
    const int tx   = tile & 15, ty = tile >> 4;

    const float fx = (float)(tx * TILE + (tid >> 4));
    const float fy = (float)(ty * TILE + (tid & 15));

    const int wbase = (tile << 5) + seg * CPS;   // 8 consecutive sub-lists, depth order
    if (tid < CPS) s_cnt[tid] = g_cnt[wbase + tid];
    __syncthreads();

    int total = 0;
    #pragma unroll
    for (int c = 0; c < CPS; ++c) total += s_cnt[c];

    float T = 1.0f, cr = 0.0f, cg = 0.0f, cb = 0.0f;

    for (int base = 0; base < total; base += 256) {
        if (base > 0 && __syncthreads_count(T >= MIN_W) == 0) break;

        const int s = base + tid;
        if (s < total) {
            int rem = s, c = 0;                  // locate sub-list
            #pragma unroll
            for (int k = 0; k < CPS - 1; ++k)
                if (rem >= s_cnt[c]) { rem -= s_cnt[c]; ++c; }
            const int gi = (int)g_idx[(wbase + c) * CAP + rem];
            s_g1[tid] = g_pa[gi];
            s_g2[tid] = g_pb[gi];
            s_cb[tid] = g_pc[gi];
        }
        const int m  = min(256, total - base);
        const int pm = (m + 7) & ~7;
        if (tid >= m && tid < pm) {              // alpha == 0 sentinels
            s_g1[tid] = make_float4(0.0f, 0.0f, 0.0f, 0.0f);
            s_g2[tid] = make_float4(0.0f, -1e30f, 0.0f, 0.0f);
            s_cb[tid] = 0.0f;
        }
        __syncthreads();

        if (T >= MIN_W) {
            for (int j = 0; j < pm; j += 8) {
                float al[8];
                #pragma unroll
                for (int k = 0; k < 8; ++k) {    // independent alpha evals (broadcast LDS)
                    const float4 g1 = s_g1[j + k];
                    const float4 g2 = s_g2[j + k];
                    const float dx = fx + g1.x;
                    const float dy = fy + g1.y;
                    float u = fmaf(g1.z, dx, g1.w * dy);
                    float q = fmaf(g2.x * dy, dy, g2.y);
                    q = fmaf(u, dx, q);
                    al[k] = ex2_fast(q);         // exp(-q/2)*sigmoid(op)
                }
                #pragma unroll
                for (int k = 0; k < 8; ++k) {    // short serial T-chain
                    const float Tn = fmaf(-al[k], T, T);
                    const float w  = (Tn >= MIN_W) ? T * al[k] : 0.0f;
                    const float4 g2 = s_g2[j + k];
                    cr = fmaf(w, g2.z, cr);
                    cg = fmaf(w, g2.w, cg);
                    cb = fmaf(w, s_cb[j + k], cb);
                    T = Tn;
                }
                if (T < MIN_W) break;            // monotone
            }
        }
    }

    const int px = tx * TILE + (tid >> 4);
    const int py = ty * TILE + (tid & 15);
    const int pix = px * H_IMG + py;
    g_scratch[seg][pix] = make_float4(cr, cg, cb, T);

    // ---- fused combine: last block per tile composites the 4 segments ----
    __threadfence();                             // publish scratch before arrival
    __syncthreads();                             // all stores in block issued
    if (tid == 0) s_ret = atomicAdd(&g_done[tile], 1);
    __syncthreads();
    if (s_ret == NSEG - 1) {
        const float4 v0 = ldcg4(&g_scratch[0][pix]);   // L2 reads (skip stale L1)
        const float4 v1 = ldcg4(&g_scratch[1][pix]);
        const float4 v2 = ldcg4(&g_scratch[2][pix]);
        const float4 v3 = ldcg4(&g_scratch[3][pix]);
        // color = c0 + T0*(c1 + T1*(c2 + T2*c3))
        float rr = fmaf(v2.w, v3.x, v2.x);
        float gg = fmaf(v2.w, v3.y, v2.y);
        float bb = fmaf(v2.w, v3.z, v2.z);
        rr = fmaf(v1.w, rr, v1.x);
        gg = fmaf(v1.w, gg, v1.y);
        bb = fmaf(v1.w, bb, v1.z);
        rr = fmaf(v0.w, rr, v0.x);
        gg = fmaf(v0.w, gg, v0.y);
        bb = fmaf(v0.w, bb, v0.z);
        out[3*pix + 0] = rr;
        out[3*pix + 1] = gg;
        out[3*pix + 2] = bb;
        if (tid == 0) g_done[tile] = 0;          // reset for next graph replay
    }
}

extern "C" void kernel_launch(void* const* d_in, const int* in_sizes, int n_in,
                              void* d_out, int out_size) {
    const float* pxy     = (const float*)d_in[0];
    const float* icov    = (const float*)d_in[1];
    const float* radius  = (const float*)d_in[2];
    const float* colors  = (const float*)d_in[3];
    const float* opacity = (const float*)d_in[4];
    float* out = (float*)d_out;

    gs_prep_kernel<<<NG / 256, 256>>>(pxy, icov, radius, colors, opacity);
    gs_bin_kernel<<<1024, 256>>>();              // 8192 warps
    dim3 rgrid(NTILE, NSEG);
    gs_raster_kernel<<<rgrid, 256>>>(out);
}

// round 10
// speedup vs baseline: 1.8732x; 1.1099x over previous
#include <cuda_runtime.h>

#define W_IMG 256
#define H_IMG 256
#define TILE 16
#define NG 8192
#define NSEG 4
#define NCHUNK 32                 // depth subchunks
#define CHUNKSZ (NG / NCHUNK)     // 256
#define CPS (NCHUNK / NSEG)       // 8 sub-lists per raster segment
#define NTILE 256
#define CAP 256
#define MIN_W 1e-6f
#define LOG2E 1.4426950408889634f
#define NPIX (W_IMG * H_IMG)

typedef unsigned long long u64;
typedef unsigned int u32;
typedef unsigned short u16;

__device__ float4 g_scratch[NSEG][NPIX];      // (cr,cg,cb,T)
__device__ u16    g_idx[NTILE * NCHUNK * CAP];// per-(tile,chunk) survivor ids (depth order)
__device__ int    g_cnt[NTILE * NCHUNK];      // exact counts
__device__ int    g_done[NTILE];              // zero-init; winner resets each run

__device__ __forceinline__ float ex2_fast(float x) {
    float y; asm("ex2.approx.f32 %0, %1;" : "=f"(y) : "f"(x)); return y;
}
__device__ __forceinline__ float lg2_fast(float x) {
    float y; asm("lg2.approx.f32 %0, %1;" : "=f"(y) : "f"(x)); return y;
}
__device__ __forceinline__ u64 pack2(float lo, float hi) {
    u64 r; asm("mov.b64 %0, {%1, %2};" : "=l"(r) : "f"(lo), "f"(hi)); return r;
}
__device__ __forceinline__ void unpack2(u64 v, float& lo, float& hi) {
    asm("mov.b64 {%0, %1}, %2;" : "=f"(lo), "=f"(hi) : "l"(v));
}
__device__ __forceinline__ u64 f2add(u64 a, u64 b) {
    u64 d; asm("add.rn.f32x2 %0, %1, %2;" : "=l"(d) : "l"(a), "l"(b)); return d;
}
__device__ __forceinline__ u64 f2mul(u64 a, u64 b) {
    u64 d; asm("mul.rn.f32x2 %0, %1, %2;" : "=l"(d) : "l"(a), "l"(b)); return d;
}
__device__ __forceinline__ u64 f2fma(u64 a, u64 b, u64 c) {
    u64 d; asm("fma.rn.f32x2 %0, %1, %2, %3;" : "=l"(d) : "l"(a), "l"(b), "l"(c)); return d;
}
__device__ __forceinline__ float4 ldcg4(const float4* p) {
    float4 v;
    asm volatile("ld.global.cg.v4.f32 {%0,%1,%2,%3}, [%4];"
                 : "=f"(v.x), "=f"(v.y), "=f"(v.z), "=f"(v.w) : "l"(p));
    return v;
}

// ---------------- bin: warp per (tile, chunk-of-256); raw cull; u16 indices ----------
__global__ __launch_bounds__(256)
void gs_bin_kernel(const float* __restrict__ pxy,
                   const float* __restrict__ radius)
{
    const int wid  = blockIdx.x * 8 + (threadIdx.x >> 5);   // 0..8191 = tile*32 + chunk
    const int lane = threadIdx.x & 31;
    const int tile = wid >> 5;
    const int chunk = wid & (NCHUNK - 1);
    const int tx = tile & 15, ty = tile >> 4;
    const float tx0 = (float)(tx * TILE), tx1 = tx0 + (float)TILE;
    const float ty0 = (float)(ty * TILE), ty1 = ty0 + (float)TILE;
    const int lbase = wid * CAP;
    const int beg = chunk * CHUNKSZ;

    int cnt = 0;
    #pragma unroll
    for (int it = 0; it < CHUNKSZ / 32; ++it) {             // 8 iterations
        const int g = beg + it * 32 + lane;
        const float2 mp = ((const float2*)pxy)[g];
        const float  r  = radius[g];
        const bool keep = (floorf(mp.x - r) <= tx1) && (ceilf(mp.x + r) >= tx0)
                       && (floorf(mp.y - r) <= ty1) && (ceilf(mp.y + r) >= ty0);
        const unsigned m = __ballot_sync(0xffffffffu, keep);
        if (keep) {
            const int idx = cnt + __popc(m & ((1u << lane) - 1u));  // order-preserving
            g_idx[lbase + idx] = (u16)g;
        }
        cnt += __popc(m);
    }
    if (lane == 0) g_cnt[wid] = cnt;
}

// ---------------- raster + fused combine; f32x2 packed composite ----------
__global__ __launch_bounds__(256)
void gs_raster_kernel(const float* __restrict__ pxy,
                      const float* __restrict__ icov,
                      const float* __restrict__ colors,
                      const float* __restrict__ opacity,
                      float* __restrict__ out)
{
    // pair-interleaved: slot j holds gaussians (2j, 2j+1)
    __shared__ ulonglong2 s_m [128];  // (-mx pair), (-my pair)
    __shared__ ulonglong2 s_ab[128];  // (a2 pair), (b2 pair)
    __shared__ ulonglong2 s_cd[128];  // (c2 pair), (d pair)
    __shared__ ulonglong2 s_rg[128];  // (r,g even), (r,g odd)
    __shared__ float2     s_b [128];  // (cb even, cb odd)
    __shared__ int        s_cnt[CPS];
    __shared__ int        s_ret;

    const int tid  = threadIdx.x;
    const int tile = blockIdx.x;
    const int seg  = blockIdx.y;
    const int tx   = tile & 15, ty = tile >> 4;

    const float fx = (float)(tx * TILE + (tid >> 4));
    const float fy = (float)(ty * TILE + (tid & 15));
    const u64 fxp = pack2(fx, fx);
    const u64 fyp = pack2(fy, fy);

    const int wbase = (tile << 5) + seg * CPS;   // 8 consecutive sub-lists, depth order
    if (tid < CPS) s_cnt[tid] = g_cnt[wbase + tid];
    __syncthreads();

    int total = 0;
    #pragma unroll
    for (int c = 0; c < CPS; ++c) total += s_cnt[c];

    float T = 1.0f;
    u64   crg = pack2(0.0f, 0.0f);
    float cb  = 0.0f;

    for (int base = 0; base < total; base += 256) {
        if (base > 0 && __syncthreads_count(T >= MIN_W) == 0) break;

        const int s = base + tid;
        if (s < total) {
            int rem = s, c = 0;                  // locate sub-list
            #pragma unroll
            for (int k = 0; k < CPS - 1; ++k)
                if (rem >= s_cnt[c]) { rem -= s_cnt[c]; ++c; }
            const int gi = (int)g_idx[(wbase + c) * CAP + rem];

            // fold constants inline (runs once per staged survivor)
            const float2 mp = ((const float2*)pxy)[gi];
            const float4 ic = ((const float4*)icov)[gi];
            const float a2 = -0.5f * LOG2E * ic.x;
            const float b2 = -LOG2E * ic.y;
            const float c2 = -0.5f * LOG2E * ic.w;
            const float d  = -lg2_fast(1.0f + ex2_fast(-LOG2E * opacity[gi])); // log2(sigmoid)

            const int j = tid >> 1, e = tid & 1;
            float* pm  = (float*)&s_m[j];  pm[e]  = -mp.x; pm[2+e]  = -mp.y;
            float* pab = (float*)&s_ab[j]; pab[e] = a2;    pab[2+e] = b2;
            float* pcd = (float*)&s_cd[j]; pcd[e] = c2;    pcd[2+e] = d;
            float* prg = (float*)&s_rg[j]; prg[2*e] = colors[3*gi+0]; prg[2*e+1] = colors[3*gi+1];
            ((float*)&s_b[j])[e] = colors[3*gi+2];
        }
        const int m  = min(256, total - base);
        const int pm8 = (m + 7) & ~7;
        if (tid >= m && tid < pm8) {             // alpha == 0 sentinels
            const int j = tid >> 1, e = tid & 1;
            float* pm  = (float*)&s_m[j];  pm[e]  = 0.0f; pm[2+e]  = 0.0f;
            float* pab = (float*)&s_ab[j]; pab[e] = 0.0f; pab[2+e] = 0.0f;
            float* pcd = (float*)&s_cd[j]; pcd[e] = 0.0f; pcd[2+e] = -1e30f;
            float* prg = (float*)&s_rg[j]; prg[2*e] = 0.0f; prg[2*e+1] = 0.0f;
            ((float*)&s_b[j])[e] = 0.0f;
        }
        __syncthreads();

        if (T >= MIN_W) {
            const int npair = pm8 >> 1;
            for (int j = 0; j < npair; j += 4) { // 4 pairs = 8 gaussians
                float al[8];
                #pragma unroll
                for (int p = 0; p < 4; ++p) {    // packed alpha evals
                    const ulonglong2 mm = s_m [j + p];
                    const ulonglong2 ab = s_ab[j + p];
                    const ulonglong2 cd = s_cd[j + p];
                    const u64 dx = f2add(fxp, mm.x);
                    const u64 dy = f2add(fyp, mm.y);
                    const u64 t1 = f2fma(ab.x, dx, f2mul(ab.y, dy));   // a2*dx + b2*dy
                    const u64 t2 = f2fma(f2mul(cd.x, dy), dy, cd.y);   // c2*dy^2 + d
                    const u64 q  = f2fma(t1, dx, t2);
                    float q0, q1; unpack2(q, q0, q1);
                    al[2*p]   = ex2_fast(q0);
                    al[2*p+1] = ex2_fast(q1);
                }
                #pragma unroll
                for (int p = 0; p < 4; ++p) {    // short serial T-chain
                    const ulonglong2 rg = s_rg[j + p];
                    const float2     bv = s_b [j + p];
                    {
                        const float a  = al[2*p];
                        const float Tn = fmaf(-a, T, T);
                        const float w  = (Tn >= MIN_W) ? T * a : 0.0f;
                        crg = f2fma(pack2(w, w), rg.x, crg);
                        cb  = fmaf(w, bv.x, cb);
                        T = Tn;
                    }
                    {
                        const float a  = al[2*p+1];
                        const float Tn = fmaf(-a, T, T);
                        const float w  = (Tn >= MIN_W) ? T * a : 0.0f;
                        crg = f2fma(pack2(w, w), rg.y, crg);
                        cb  = fmaf(w, bv.y, cb);
                        T = Tn;
                    }
                }
                if (T < MIN_W) break;            // monotone
            }
        }
    }

    float cr, cg; unpack2(crg, cr, cg);
    const int px = tx * TILE + (tid >> 4);
    const int py = ty * TILE + (tid & 15);
    const int pix = px * H_IMG + py;
    g_scratch[seg][pix] = make_float4(cr, cg, cb, T);

    // ---- fused combine: last block per tile composites the 4 segments ----
    __threadfence();
    __syncthreads();
    if (tid == 0) s_ret = atomicAdd(&g_done[tile], 1);
    __syncthreads();
    if (s_ret == NSEG - 1) {
        const float4 v0 = ldcg4(&g_scratch[0][pix]);
        const float4 v1 = ldcg4(&g_scratch[1][pix]);
        const float4 v2 = ldcg4(&g_scratch[2][pix]);
        const float4 v3 = ldcg4(&g_scratch[3][pix]);
        float rr = fmaf(v2.w, v3.x, v2.x);
        float gg = fmaf(v2.w, v3.y, v2.y);
        float bb = fmaf(v2.w, v3.z, v2.z);
        rr = fmaf(v1.w, rr, v1.x);
        gg = fmaf(v1.w, gg, v1.y);
        bb = fmaf(v1.w, bb, v1.z);
        rr = fmaf(v0.w, rr, v0.x);
        gg = fmaf(v0.w, gg, v0.y);
        bb = fmaf(v0.w, bb, v0.z);
        out[3*pix + 0] = rr;
        out[3*pix + 1] = gg;
        out[3*pix + 2] = bb;
        if (tid == 0) g_done[tile] = 0;          // reset for next graph replay
    }
}

extern "C" void kernel_launch(void* const* d_in, const int* in_sizes, int n_in,
                              void* d_out, int out_size) {
    const float* pxy     = (const float*)d_in[0];
    const float* icov    = (const float*)d_in[1];
    const float* radius  = (const float*)d_in[2];
    const float* colors  = (const float*)d_in[3];
    const float* opacity = (const float*)d_in[4];
    float* out = (float*)d_out;

    gs_bin_kernel<<<1024, 256>>>(pxy, radius);   // 8192 warps
    dim3 rgrid(NTILE, NSEG);
    gs_raster_kernel<<<rgrid, 256>>>(pxy, icov, colors, opacity, out);
}

// round 11
// speedup vs baseline: 2.1045x; 1.1235x over previous
#include <cuda_runtime.h>

#define W_IMG 256
#define H_IMG 256
#define TILE 16
#define NG 8192
#define NSEG 4
#define SEG (NG / NSEG)           // 2048 gaussians per segment
#define CPS 8                     // chunks per segment (1 per warp)
#define CHUNKSZ (SEG / CPS)       // 256
#define NTILE 256
#define MIN_W 1e-6f
#define LOG2E 1.4426950408889634f
#define NPIX (W_IMG * H_IMG)

typedef unsigned long long u64;
typedef unsigned short u16;

__device__ float4 g_scratch[NSEG][NPIX];   // (cr,cg,cb,T)
__device__ int    g_done[NTILE];           // zero-init; winner resets each run

__device__ __forceinline__ float ex2_fast(float x) {
    float y; asm("ex2.approx.f32 %0, %1;" : "=f"(y) : "f"(x)); return y;
}
__device__ __forceinline__ float lg2_fast(float x) {
    float y; asm("lg2.approx.f32 %0, %1;" : "=f"(y) : "f"(x)); return y;
}
__device__ __forceinline__ u64 pack2(float lo, float hi) {
    u64 r; asm("mov.b64 %0, {%1, %2};" : "=l"(r) : "f"(lo), "f"(hi)); return r;
}
__device__ __forceinline__ void unpack2(u64 v, float& lo, float& hi) {
    asm("mov.b64 {%0, %1}, %2;" : "=f"(lo), "=f"(hi) : "l"(v));
}
__device__ __forceinline__ u64 f2add(u64 a, u64 b) {
    u64 d; asm("add.rn.f32x2 %0, %1, %2;" : "=l"(d) : "l"(a), "l"(b)); return d;
}
__device__ __forceinline__ u64 f2mul(u64 a, u64 b) {
    u64 d; asm("mul.rn.f32x2 %0, %1, %2;" : "=l"(d) : "l"(a), "l"(b)); return d;
}
__device__ __forceinline__ u64 f2fma(u64 a, u64 b, u64 c) {
    u64 d; asm("fma.rn.f32x2 %0, %1, %2, %3;" : "=l"(d) : "l"(a), "l"(b), "l"(c)); return d;
}
__device__ __forceinline__ float4 ldcg4(const float4* p) {
    float4 v;
    asm volatile("ld.global.cg.v4.f32 {%0,%1,%2,%3}, [%4];"
                 : "=f"(v.x), "=f"(v.y), "=f"(v.z), "=f"(v.w) : "l"(p));
    return v;
}

// ------------- fused: cull (per-warp, smem lists) + staged f32x2 composite + combine -------------
__global__ __launch_bounds__(256)
void gs_raster_kernel(const float* __restrict__ pxy,
                      const float* __restrict__ icov,
                      const float* __restrict__ radius,
                      const float* __restrict__ colors,
                      const float* __restrict__ opacity,
                      float* __restrict__ out)
{
    __shared__ u16        s_idx[SEG];   // survivor ids, depth order within each chunk
    __shared__ int        s_cnt[CPS];
    // pair-interleaved composite staging: slot j holds gaussians (2j, 2j+1)
    __shared__ ulonglong2 s_m [128];    // (-mx pair), (-my pair)
    __shared__ ulonglong2 s_ab[128];    // (a2 pair), (b2 pair)
    __shared__ ulonglong2 s_cd[128];    // (c2 pair), (d pair)
    __shared__ ulonglong2 s_rg[128];    // (r,g even), (r,g odd)
    __shared__ float2     s_b [128];    // (cb even, cb odd)
    __shared__ int        s_ret;

    const int tid  = threadIdx.x;
    const int lane = tid & 31;
    const int warp = tid >> 5;
    const int tile = blockIdx.x;
    const int seg  = blockIdx.y;
    const int tx   = tile & 15, ty = tile >> 4;

    // ---- cull phase: warp w culls chunk w of this block's segment ----
    {
        const float tx0 = (float)(tx * TILE), tx1 = tx0 + (float)TILE;
        const float ty0 = (float)(ty * TILE), ty1 = ty0 + (float)TILE;
        const int beg = seg * SEG + warp * CHUNKSZ;
        int cnt = 0;
        #pragma unroll
        for (int it = 0; it < CHUNKSZ / 32; ++it) {          // 8 iterations
            const int g = beg + it * 32 + lane;
            const float2 mp = ((const float2*)pxy)[g];
            const float  r  = radius[g];
            const bool keep = (floorf(mp.x - r) <= tx1) && (ceilf(mp.x + r) >= tx0)
                           && (floorf(mp.y - r) <= ty1) && (ceilf(mp.y + r) >= ty0);
            const unsigned m = __ballot_sync(0xffffffffu, keep);
            if (keep) {
                const int idx = cnt + __popc(m & ((1u << lane) - 1u));  // order-preserving
                s_idx[warp * CHUNKSZ + idx] = (u16)g;
            }
            cnt += __popc(m);
        }
        if (lane == 0) s_cnt[warp] = cnt;
    }
    __syncthreads();

    int total = 0;
    #pragma unroll
    for (int c = 0; c < CPS; ++c) total += s_cnt[c];

    const float fx = (float)(tx * TILE + (tid >> 4));
    const float fy = (float)(ty * TILE + (tid & 15));
    const u64 fxp = pack2(fx, fx);
    const u64 fyp = pack2(fy, fy);

    float T = 1.0f;
    u64   crg = pack2(0.0f, 0.0f);
    float cb  = 0.0f;

    for (int base = 0; base < total; base += 256) {
        if (base > 0 && __syncthreads_count(T >= MIN_W) == 0) break;

        const int s = base + tid;
        if (s < total) {
            int rem = s, c = 0;                   // locate sub-list (8 per-warp chunks)
            #pragma unroll
            for (int k = 0; k < CPS - 1; ++k)
                if (rem >= s_cnt[c]) { rem -= s_cnt[c]; ++c; }
            const int gi = (int)s_idx[c * CHUNKSZ + rem];

            // fold constants inline (once per staged survivor)
            const float2 mp = ((const float2*)pxy)[gi];
            const float4 ic = ((const float4*)icov)[gi];
            const float a2 = -0.5f * LOG2E * ic.x;
            const float b2 = -LOG2E * ic.y;
            const float c2 = -0.5f * LOG2E * ic.w;
            const float d  = -lg2_fast(1.0f + ex2_fast(-LOG2E * opacity[gi])); // log2(sigmoid)

            const int j = tid >> 1, e = tid & 1;
            float* pm  = (float*)&s_m[j];  pm[e]  = -mp.x; pm[2+e]  = -mp.y;
            float* pab = (float*)&s_ab[j]; pab[e] = a2;    pab[2+e] = b2;
            float* pcd = (float*)&s_cd[j]; pcd[e] = c2;    pcd[2+e] = d;
            float* prg = (float*)&s_rg[j]; prg[2*e] = colors[3*gi+0]; prg[2*e+1] = colors[3*gi+1];
            ((float*)&s_b[j])[e] = colors[3*gi+2];
        }
        const int m   = min(256, total - base);
        const int pm8 = (m + 7) & ~7;
        if (tid >= m && tid < pm8) {              // alpha == 0 sentinels
            const int j = tid >> 1, e = tid & 1;
            float* pm  = (float*)&s_m[j];  pm[e]  = 0.0f; pm[2+e]  = 0.0f;
            float* pab = (float*)&s_ab[j]; pab[e] = 0.0f; pab[2+e] = 0.0f;
            float* pcd = (float*)&s_cd[j]; pcd[e] = 0.0f; pcd[2+e] = -1e30f;
            float* prg = (float*)&s_rg[j]; prg[2*e] = 0.0f; prg[2*e+1] = 0.0f;
            ((float*)&s_b[j])[e] = 0.0f;
        }
        __syncthreads();

        if (T >= MIN_W) {
            const int npair = pm8 >> 1;
            for (int j = 0; j < npair; j += 4) {  // 4 pairs = 8 gaussians
                float al[8];
                #pragma unroll
                for (int p = 0; p < 4; ++p) {     // packed alpha evals
                    const ulonglong2 mm = s_m [j + p];
                    const ulonglong2 ab = s_ab[j + p];
                    const ulonglong2 cd = s_cd[j + p];
                    const u64 dx = f2add(fxp, mm.x);
                    const u64 dy = f2add(fyp, mm.y);
                    const u64 t1 = f2fma(ab.x, dx, f2mul(ab.y, dy));   // a2*dx + b2*dy
                    const u64 t2 = f2fma(f2mul(cd.x, dy), dy, cd.y);   // c2*dy^2 + d
                    const u64 q  = f2fma(t1, dx, t2);
                    float q0, q1; unpack2(q, q0, q1);
                    al[2*p]   = ex2_fast(q0);
                    al[2*p+1] = ex2_fast(q1);
                }
                #pragma unroll
                for (int p = 0; p < 4; ++p) {     // short serial T-chain
                    const ulonglong2 rg = s_rg[j + p];
                    const float2     bv = s_b [j + p];
                    {
                        const float a  = al[2*p];
                        const float Tn = fmaf(-a, T, T);
                        const float w  = (Tn >= MIN_W) ? T * a : 0.0f;
                        crg = f2fma(pack2(w, w), rg.x, crg);
                        cb  = fmaf(w, bv.x, cb);
                        T = Tn;
                    }
                    {
                        const float a  = al[2*p+1];
                        const float Tn = fmaf(-a, T, T);
                        const float w  = (Tn >= MIN_W) ? T * a : 0.0f;
                        crg = f2fma(pack2(w, w), rg.y, crg);
                        cb  = fmaf(w, bv.y, cb);
                        T = Tn;
                    }
                }
                if (T < MIN_W) break;             // monotone
            }
        }
    }

    float cr, cg; unpack2(crg, cr, cg);
    const int px = tx * TILE + (tid >> 4);
    const int py = ty * TILE + (tid & 15);
    const int pix = px * H_IMG + py;
    g_scratch[seg][pix] = make_float4(cr, cg, cb, T);

    // ---- fused combine: last block per tile composites the 4 segments ----
    __threadfence();
    __syncthreads();
    if (tid == 0) s_ret = atomicAdd(&g_done[tile], 1);
    __syncthreads();
    if (s_ret == NSEG - 1) {
        const float4 v0 = ldcg4(&g_scratch[0][pix]);
        const float4 v1 = ldcg4(&g_scratch[1][pix]);
        const float4 v2 = ldcg4(&g_scratch[2][pix]);
        const float4 v3 = ldcg4(&g_scratch[3][pix]);
        // color = c0 + T0*(c1 + T1*(c2 + T2*c3))
        float rr = fmaf(v2.w, v3.x, v2.x);
        float gg = fmaf(v2.w, v3.y, v2.y);
        float bb = fmaf(v2.w, v3.z, v2.z);
        rr = fmaf(v1.w, rr, v1.x);
        gg = fmaf(v1.w, gg, v1.y);
        bb = fmaf(v1.w, bb, v1.z);
        rr = fmaf(v0.w, rr, v0.x);
        gg = fmaf(v0.w, gg, v0.y);
        bb = fmaf(v0.w, bb, v0.z);
        out[3*pix + 0] = rr;
        out[3*pix + 1] = gg;
        out[3*pix + 2] = bb;
        if (tid == 0) g_done[tile] = 0;           // reset for next graph replay
    }
}

extern "C" void kernel_launch(void* const* d_in, const int* in_sizes, int n_in,
                              void* d_out, int out_size) {
    const float* pxy     = (const float*)d_in[0];
    const float* icov    = (const float*)d_in[1];
    const float* radius  = (const float*)d_in[2];
    const float* colors  = (const float*)d_in[3];
    const float* opacity = (const float*)d_in[4];
    float* out = (float*)d_out;

    dim3 rgrid(NTILE, NSEG);
    gs_raster_kernel<<<rgrid, 256>>>(pxy, icov, radius, colors, opacity, out);
}